// round 4
// baseline (speedup 1.0000x reference)
#include <cuda_runtime.h>
#include <cstdint>

// Problem dims (fixed by the reference)
#define B_ 256
#define T_ 512
#define D_ 1024
#define H_ 2048
#define O_ 32

// 1 GiB scratch for PRE = X @ W1[:D] + b1, laid out [B*T, H]
__device__ float g_pre[(size_t)B_ * T_ * H_];

// ---------------------------------------------------------------------------
// Kernel 1: fp32 SGEMM  PRE[m, n] = sum_k X[m,k] * W1[k,n] + b1[n]
//   M = B*T = 131072, K = D = 1024, N = H = 2048
//   128x128 block tile, K-tile 8, 256 threads, 8x8 micro-tile, double-buffered
// ---------------------------------------------------------------------------
__global__ __launch_bounds__(256, 2) void gemm1_kernel(
    const float* __restrict__ X,
    const float* __restrict__ W1,
    const float* __restrict__ b1)
{
    const int K = D_;
    const int N = H_;

    __shared__ float As[2][8][128];   // A transposed: As[k][m]
    __shared__ float Bs[2][8][128];   // Bs[k][n]

    const int bm = blockIdx.y * 128;
    const int bn = blockIdx.x * 128;
    const int tid = threadIdx.x;

    // A-tile load mapping: 256 threads x float4 = 128 rows x 8 k
    const int am = tid >> 1;            // 0..127 (row in tile)
    const int ak = (tid & 1) * 4;       // 0 or 4 (k offset)
    // B-tile load mapping: 8 k-rows x 128 cols
    const int bk = tid >> 5;            // 0..7
    const int bc = (tid & 31) * 4;      // 0..124

    const float* Aptr = X  + (size_t)(bm + am) * K + ak;
    const float* Bptr = W1 + (size_t)bk * N + bn + bc;

    // Preload tile 0
    {
        float4 a4 = *(const float4*)Aptr;
        float4 b4 = *(const float4*)Bptr;
        As[0][ak + 0][am] = a4.x;
        As[0][ak + 1][am] = a4.y;
        As[0][ak + 2][am] = a4.z;
        As[0][ak + 3][am] = a4.w;
        *(float4*)&Bs[0][bk][bc] = b4;
    }
    __syncthreads();

    const int tx = tid & 15;   // 0..15 -> n micro
    const int ty = tid >> 4;   // 0..15 -> m micro

    float acc[8][8];
#pragma unroll
    for (int i = 0; i < 8; ++i)
#pragma unroll
        for (int j = 0; j < 8; ++j) acc[i][j] = 0.0f;

    int buf = 0;
    for (int kt = 8;; kt += 8) {
        const bool more = (kt < K);
        float4 na, nb;
        if (more) {
            na = *(const float4*)(Aptr + kt);
            nb = *(const float4*)(Bptr + (size_t)kt * N);
        }
#pragma unroll
        for (int k = 0; k < 8; ++k) {
            float a[8], b[8];
            *(float4*)(&a[0]) = *(const float4*)(&As[buf][k][ty * 8]);
            *(float4*)(&a[4]) = *(const float4*)(&As[buf][k][ty * 8 + 4]);
            *(float4*)(&b[0]) = *(const float4*)(&Bs[buf][k][tx * 8]);
            *(float4*)(&b[4]) = *(const float4*)(&Bs[buf][k][tx * 8 + 4]);
#pragma unroll
            for (int i = 0; i < 8; ++i)
#pragma unroll
                for (int j = 0; j < 8; ++j)
                    acc[i][j] = fmaf(a[i], b[j], acc[i][j]);
        }
        if (!more) break;
        buf ^= 1;
        As[buf][ak + 0][am] = na.x;
        As[buf][ak + 1][am] = na.y;
        As[buf][ak + 2][am] = na.z;
        As[buf][ak + 3][am] = na.w;
        *(float4*)&Bs[buf][bk][bc] = nb;
        __syncthreads();
    }

    // Epilogue: add b1, store
    const float4 bv0 = *(const float4*)(b1 + bn + tx * 8);
    const float4 bv1 = *(const float4*)(b1 + bn + tx * 8 + 4);
#pragma unroll
    for (int i = 0; i < 8; ++i) {
        const size_t row = (size_t)(bm + ty * 8 + i);
        float* op = g_pre + row * N + bn + tx * 8;
        float4 o0, o1;
        o0.x = acc[i][0] + bv0.x; o0.y = acc[i][1] + bv0.y;
        o0.z = acc[i][2] + bv0.z; o0.w = acc[i][3] + bv0.w;
        o1.x = acc[i][4] + bv1.x; o1.y = acc[i][5] + bv1.y;
        o1.z = acc[i][6] + bv1.z; o1.w = acc[i][7] + bv1.w;
        *(float4*)op       = o0;
        *(float4*)(op + 4) = o1;
    }
}

// ---------------------------------------------------------------------------
// Kernel 2: sequential greedy decode, batch-parallel.
//   128 blocks x 256 threads; block g owns batch rows (2g, 2g+1).
//   Per step t:
//     h[j]   = tanh(PRE[b,t,j] + W1[D + prev_pred[b], j])      (b1 folded in)
//     logit  = h @ W2 + b2      -> argmax -> feedback
// ---------------------------------------------------------------------------
__global__ __launch_bounds__(256, 1) void seq_kernel(
    const float* __restrict__ W1,
    const float* __restrict__ W2,
    const float* __restrict__ b2,
    float* __restrict__ logits_out,
    char* __restrict__ pred_out,
    int pred_mode)   // 0: none, 1: float32, 2: int64
{
    __shared__ float hs[2][H_];        // 16 KB
    __shared__ float red[8][2][O_];    //  2 KB
    __shared__ int   spred[2];

    const int tid = threadIdx.x;
    const int w = tid >> 5;
    const int l = tid & 31;
    const int b0 = blockIdx.x * 2;

    if (tid < 2) spred[tid] = 0;       // class 0 at t=0

    const int j0 = tid * 8;
    const float* preA = g_pre + (size_t)b0 * T_ * H_ + j0;
    const float* preB = g_pre + (size_t)(b0 + 1) * T_ * H_ + j0;

    float4 cur[2][2], nxt[2][2];
    cur[0][0] = *(const float4*)(preA);
    cur[0][1] = *(const float4*)(preA + 4);
    cur[1][0] = *(const float4*)(preB);
    cur[1][1] = *(const float4*)(preB + 4);
    __syncthreads();

    for (int t = 0; t < T_; ++t) {
        // Prefetch next step's PRE rows (independent of preds) to hide HBM.
        if (t + 1 < T_) {
            const float* pA = preA + (size_t)(t + 1) * H_;
            const float* pB = preB + (size_t)(t + 1) * H_;
            nxt[0][0] = __ldg((const float4*)pA);
            nxt[0][1] = __ldg((const float4*)(pA + 4));
            nxt[1][0] = __ldg((const float4*)pB);
            nxt[1][1] = __ldg((const float4*)(pB + 4));
        }

        // ---- Phase A: h = tanh(pre + W1[D+prev]) -> smem
        const int p0 = spred[0];
        const int p1 = spred[1];
        const float* r0 = W1 + (size_t)(D_ + p0) * H_ + j0;
        const float* r1 = W1 + (size_t)(D_ + p1) * H_ + j0;
        const float4 w00 = __ldg((const float4*)r0);
        const float4 w01 = __ldg((const float4*)(r0 + 4));
        const float4 w10 = __ldg((const float4*)r1);
        const float4 w11 = __ldg((const float4*)(r1 + 4));

        float4 h;
        h.x = tanhf(cur[0][0].x + w00.x); h.y = tanhf(cur[0][0].y + w00.y);
        h.z = tanhf(cur[0][0].z + w00.z); h.w = tanhf(cur[0][0].w + w00.w);
        *(float4*)&hs[0][j0] = h;
        h.x = tanhf(cur[0][1].x + w01.x); h.y = tanhf(cur[0][1].y + w01.y);
        h.z = tanhf(cur[0][1].z + w01.z); h.w = tanhf(cur[0][1].w + w01.w);
        *(float4*)&hs[0][j0 + 4] = h;
        h.x = tanhf(cur[1][0].x + w10.x); h.y = tanhf(cur[1][0].y + w10.y);
        h.z = tanhf(cur[1][0].z + w10.z); h.w = tanhf(cur[1][0].w + w10.w);
        *(float4*)&hs[1][j0] = h;
        h.x = tanhf(cur[1][1].x + w11.x); h.y = tanhf(cur[1][1].y + w11.y);
        h.z = tanhf(cur[1][1].z + w11.z); h.w = tanhf(cur[1][1].w + w11.w);
        *(float4*)&hs[1][j0 + 4] = h;
        __syncthreads();

        // ---- Phase B: logits = h @ W2
        // warp w covers j in [w*256, w*256+256); lane = (js, oq):
        //   js = l>>3 handles j = base + it*4 + js  (4 consecutive j per iter
        //   -> conflict-free smem broadcast, 4 full 128B lines per LDG.128)
        //   oq = l&7 handles outputs [4*oq, 4*oq+4) via one float4 W2 load.
        const int oq = l & 7;
        const int js = l >> 3;
        const int jb = w * 256;
        float a0x = 0.f, a0y = 0.f, a0z = 0.f, a0w = 0.f;
        float a1x = 0.f, a1y = 0.f, a1z = 0.f, a1w = 0.f;
#pragma unroll 8
        for (int it = 0; it < 64; ++it) {
            const int j = jb + it * 4 + js;
            const float4 wv = __ldg((const float4*)(W2 + (size_t)j * O_ + oq * 4));
            const float h0 = hs[0][j];
            const float h1 = hs[1][j];
            a0x = fmaf(h0, wv.x, a0x); a0y = fmaf(h0, wv.y, a0y);
            a0z = fmaf(h0, wv.z, a0z); a0w = fmaf(h0, wv.w, a0w);
            a1x = fmaf(h1, wv.x, a1x); a1y = fmaf(h1, wv.y, a1y);
            a1z = fmaf(h1, wv.z, a1z); a1w = fmaf(h1, wv.w, a1w);
        }
        // Reduce over the 4 js-lanes (xor 8, 16)
#pragma unroll
        for (int m = 8; m <= 16; m <<= 1) {
            a0x += __shfl_xor_sync(0xffffffffu, a0x, m);
            a0y += __shfl_xor_sync(0xffffffffu, a0y, m);
            a0z += __shfl_xor_sync(0xffffffffu, a0z, m);
            a0w += __shfl_xor_sync(0xffffffffu, a0w, m);
            a1x += __shfl_xor_sync(0xffffffffu, a1x, m);
            a1y += __shfl_xor_sync(0xffffffffu, a1y, m);
            a1z += __shfl_xor_sync(0xffffffffu, a1z, m);
            a1w += __shfl_xor_sync(0xffffffffu, a1w, m);
        }
        if (js == 0) {
            *(float4*)&red[w][0][oq * 4] = make_float4(a0x, a0y, a0z, a0w);
            *(float4*)&red[w][1][oq * 4] = make_float4(a1x, a1y, a1z, a1w);
        }
        __syncthreads();

        // ---- Final: warp 0 sums 8 warps, writes logits, argmax, feedback
        if (w == 0) {
            const float bb = __ldg(b2 + l);
            float s0 = bb, s1 = bb;
#pragma unroll
            for (int wi = 0; wi < 8; ++wi) {
                s0 += red[wi][0][l];
                s1 += red[wi][1][l];
            }
            logits_out[((size_t)b0 * T_ + t) * O_ + l]       = s0;
            logits_out[((size_t)(b0 + 1) * T_ + t) * O_ + l] = s1;

            // argmax over 32 lanes, first-max (lowest index) tie-break
            float v = s0; int idx = l;
#pragma unroll
            for (int m = 16; m >= 1; m >>= 1) {
                const float v2 = __shfl_xor_sync(0xffffffffu, v, m);
                const int   i2 = __shfl_xor_sync(0xffffffffu, idx, m);
                if (v2 > v || (v2 == v && i2 < idx)) { v = v2; idx = i2; }
            }
            const int idx0 = idx;
            v = s1; idx = l;
#pragma unroll
            for (int m = 16; m >= 1; m >>= 1) {
                const float v2 = __shfl_xor_sync(0xffffffffu, v, m);
                const int   i2 = __shfl_xor_sync(0xffffffffu, idx, m);
                if (v2 > v || (v2 == v && i2 < idx)) { v = v2; idx = i2; }
            }
            const int idx1 = idx;

            if (l == 0) {
                spred[0] = idx0;
                spred[1] = idx1;
                const size_t pi0 = (size_t)b0 * T_ + t;
                const size_t pi1 = pi0 + T_;
                if (pred_mode == 1) {
                    ((float*)pred_out)[pi0] = (float)idx0;
                    ((float*)pred_out)[pi1] = (float)idx1;
                } else if (pred_mode == 2) {
                    ((long long*)pred_out)[pi0] = (long long)idx0;
                    ((long long*)pred_out)[pi1] = (long long)idx1;
                }
            }
        }
        __syncthreads();   // spred ready for next step

        cur[0][0] = nxt[0][0]; cur[0][1] = nxt[0][1];
        cur[1][0] = nxt[1][0]; cur[1][1] = nxt[1][1];
    }
}

// ---------------------------------------------------------------------------
// Launch
// ---------------------------------------------------------------------------
extern "C" void kernel_launch(void* const* d_in, const int* in_sizes, int n_in,
                              void* d_out, int out_size)
{
    const float* x  = (const float*)d_in[0];   // [B, T, D]
    const float* W1 = (const float*)d_in[1];   // [D+O, H]
    const float* b1 = (const float*)d_in[2];   // [H]
    const float* W2 = (const float*)d_in[3];   // [H, O]
    const float* b2 = (const float*)d_in[4];   // [O]
    float* out = (float*)d_out;

    // Phase 1: big parallel GEMM into scratch
    dim3 grid1(H_ / 128, (B_ * T_) / 128);     // (16, 1024)
    gemm1_kernel<<<grid1, 256>>>(x, W1, b1);

    // Output layout adaptation: logits first, then preds (layout per out_size)
    const long long LOGN = (long long)B_ * T_ * O_;   // 4194304
    const long long PN   = (long long)B_ * T_;        // 131072
    char* pbase = (char*)d_out + (size_t)LOGN * sizeof(float);
    int mode;
    const long long os = (long long)out_size;
    if (os == LOGN + PN)            mode = 1;   // preds as float32
    else if (os == LOGN + 2 * PN)   mode = 2;   // preds as raw int64
    else if (os == LOGN)            mode = 0;   // logits only
    else                            mode = 1;   // best guess

    // Phase 2: sequential decode, 2 batch rows per block
    seq_kernel<<<B_ / 2, 256>>>(W1, W2, b2, out, pbase, mode);
}